// round 16
// baseline (speedup 1.0000x reference)
#include <cuda_runtime.h>
#include <cstdint>
#include <math.h>

// ---------------- problem constants ----------------
#define BCH 4
#define SEQ 2048
#define CH  1024
#define NH  16
#define HD  64
#define LR  20
#define RS  200
#define QKW (2*CH)
#define MTOT (BCH*SEQ)    // 8192
#define BK   32
#define STAGE_FLT (2*128*32)   // 32 KB per pipeline stage
#define NBH (BCH*NH)      // 64
#define KS2  640               // rank-structured K for the output gemm

// ---------------- scratch (device globals) ----------------
__device__ __align__(256) float g_xr[(size_t)MTOT * CH];
__device__ __align__(256) float g_qkwr[(size_t)QKW * CH];
__device__ __align__(256) float g_webT[(size_t)NBH * LR * HD];  // [bh][j][d]
__device__ __align__(256) float g_wrbT[(size_t)NBH * LR * HD];
__device__ __align__(256) float g_S[(size_t)MTOT * KS2];        // [b*n][h*40+j]
__device__ __align__(256) float g_Bg[(size_t)CH * KS2];         // [o][hj]
__device__ __align__(256) float g_obias[CH];

// ---------------- helpers ----------------
__device__ __forceinline__ float tf32r(float x) {
    float y;
    asm("cvt.rna.tf32.f32 %0, %1;" : "=f"(y) : "f"(x));
    return y;
}
__device__ __forceinline__ uint32_t smem_u32(const void* p) {
    uint32_t a;
    asm("{ .reg .u64 t; cvta.to.shared.u64 t, %1; cvt.u32.u64 %0, t; }"
        : "=r"(a) : "l"(p));
    return a;
}
#define CP_ASYNC16(dst, src) \
    asm volatile("cp.async.cg.shared.global [%0], [%1], 16;" :: "r"(dst), "l"(src))
#define CP_COMMIT() asm volatile("cp.async.commit_group;" ::: "memory")
#define CP_WAIT1()  asm volatile("cp.async.wait_group 1;" ::: "memory")

__device__ __forceinline__ void mma8(float* d, const float* a, const float* b) {
    asm volatile(
        "mma.sync.aligned.m16n8k8.row.col.f32.tf32.tf32.f32 "
        "{%0,%1,%2,%3}, {%4,%5,%6,%7}, {%8,%9}, {%0,%1,%2,%3};"
        : "+f"(d[0]), "+f"(d[1]), "+f"(d[2]), "+f"(d[3])
        : "r"(__float_as_uint(a[0])), "r"(__float_as_uint(a[1])),
          "r"(__float_as_uint(a[2])), "r"(__float_as_uint(a[3])),
          "r"(__float_as_uint(b[0])), "r"(__float_as_uint(b[1])));
}

// shared mainloop pieces (128 threads, 4 warps, warp tile 64x64) -------------
#define GEMM_PROLOG()                                                          \
    const int tid = threadIdx.x;                                               \
    const int wid = tid >> 5, lane = tid & 31;                                 \
    const int wm = wid >> 1;          /* 0..1 -> m offset 64*wm */             \
    const int wn = wid & 1;           /* 0..1 -> n offset 64*wn */             \
    const int gid = lane >> 2;                                                 \
    const int tig = lane & 3;                                                  \
    (void)lane;

#define COPY_STAGE(s, Kdim) do {                                               \
        const int _k0 = (s) * BK;                                              \
        const uint32_t _db = sbase + ((s) % 3) * (STAGE_FLT * 4);              \
        _Pragma("unroll")                                                      \
        for (int _i = 0; _i < 16; _i++) {                                      \
            int _id  = _i * 128 + tid;                                         \
            int _mat = _id >> 10;                                              \
            int _row = (_id >> 3) & 127;                                       \
            int _ch  = _id & 7;                                                \
            const float* _src = (_mat ? (B + (size_t)(n0 + _row) * (Kdim))     \
                                      : (A + (size_t)(m0 + _row) * (Kdim)))    \
                                + _k0 + _ch * 4;                               \
            uint32_t _dst = _db + (uint32_t)(_mat * 4096 + _row * 32 +         \
                                   ((_ch ^ (_row & 7)) << 2)) * 4u;            \
            CP_ASYNC16(_dst, _src);                                            \
        }                                                                      \
    } while (0)

// fragment load for one ks slice
#define FRAG_LOAD(ks)                                                          \
    do {                                                                       \
        const int x0 = ((((ks) >> 2)     ) ^ gid) << 2;                        \
        const int x1 = ((((ks) >> 2) + 1) ^ gid) << 2;                         \
        _Pragma("unroll")                                                      \
        for (int mt = 0; mt < 4; mt++) {                                       \
            af[mt][0] = As[mbase[mt] + x0];                                    \
            af[mt][1] = As[mbase[mt] + 256 + x0];                              \
            af[mt][2] = As[mbase[mt] + x1];                                    \
            af[mt][3] = As[mbase[mt] + 256 + x1];                              \
        }                                                                      \
        _Pragma("unroll")                                                      \
        for (int nt = 0; nt < 8; nt++) {                                       \
            bf[nt][0] = Bs[nbase[nt] + x0];                                    \
            bf[nt][1] = Bs[nbase[nt] + x1];                                    \
        }                                                                      \
    } while (0)

#define MMA_STEP()                                                             \
    _Pragma("unroll")                                                          \
    for (int mt = 0; mt < 4; mt++)                                             \
        _Pragma("unroll")                                                      \
        for (int nt = 0; nt < 8; nt++)                                         \
            mma8(acc[mt][nt], af[mt], bf[nt]);

// Stage order: wait -> bar -> load ks=0 frags -> issue next copy -> MMA(ks=0)
// -> remaining ks slices. The first MMA batch overlaps the LDGSTS issue burst.
#define GEMM_MAINLOOP(Kdim, nst)                                               \
    COPY_STAGE(0, Kdim); CP_COMMIT();                                          \
    COPY_STAGE(1, Kdim); CP_COMMIT();                                          \
    float acc[4][8][4];                                                        \
    _Pragma("unroll")                                                          \
    for (int mt = 0; mt < 4; mt++)                                             \
        _Pragma("unroll")                                                      \
        for (int nt = 0; nt < 8; nt++)                                         \
            _Pragma("unroll")                                                  \
            for (int r = 0; r < 4; r++) acc[mt][nt][r] = 0.f;                  \
    int mbase[4], nbase[8];                                                    \
    _Pragma("unroll")                                                          \
    for (int mt = 0; mt < 4; mt++)                                             \
        mbase[mt] = (wm * 64 + mt * 16 + gid) * 32 + tig;                      \
    _Pragma("unroll")                                                          \
    for (int nt = 0; nt < 8; nt++)                                             \
        nbase[nt] = (wn * 64 + nt * 8 + gid) * 32 + tig;                       \
    for (int c = 0; c < (nst); c++) {                                          \
        CP_WAIT1();                                                            \
        __syncthreads();                                                       \
        const float* As = sm + (c % 3) * STAGE_FLT;                            \
        const float* Bs = As + 4096;                                           \
        float af[4][4], bf[8][2];                                              \
        FRAG_LOAD(0);                                                          \
        if (c + 2 < (nst)) COPY_STAGE(c + 2, Kdim);                            \
        CP_COMMIT();                                                           \
        MMA_STEP();                                                            \
        _Pragma("unroll")                                                      \
        for (int ks = 8; ks < BK; ks += 8) {                                   \
            FRAG_LOAD(ks);                                                     \
            MMA_STEP();                                                        \
        }                                                                      \
    }

// ---------------- round pass: x and qk_w -> tf32 grid (no smem) ------------
__global__ __launch_bounds__(256) void round_kernel(
    const float* __restrict__ x, const float* __restrict__ qkw,
    float* __restrict__ xr, float* __restrict__ qkwr)
{
    const int X4 = MTOT * CH / 4;
    const int T4 = X4 + QKW * CH / 4;
    for (int i = blockIdx.x * 256 + threadIdx.x; i < T4;
         i += gridDim.x * 256) {
        if (i < X4) {
            float4 v = ((const float4*)x)[i];
            v.x = tf32r(v.x); v.y = tf32r(v.y);
            v.z = tf32r(v.z); v.w = tf32r(v.w);
            ((float4*)xr)[i] = v;
        } else {
            int j = i - X4;
            float4 v = ((const float4*)qkw)[j];
            v.x = tf32r(v.x); v.y = tf32r(v.y);
            v.z = tf32r(v.z); v.w = tf32r(v.w);
            ((float4*)qkwr)[j] = v;
        }
    }
}

// ---------------- prep: gen_weights (0..63) + gprep (64..127) ---------------
#define PR_XH 0
#define PR_WE (PR_XH + RS*HD)
#define PR_WR (PR_WE + RS*LR)
#define PR_TOT (PR_WR + RS*LR)   // 20800 floats
__global__ __launch_bounds__(256) void prep_kernel(
    const float* __restrict__ x,
    const float* __restrict__ we, const float* __restrict__ wr,
    const float* __restrict__ proj_w, const float* __restrict__ cw_w,
    const float* __restrict__ proj_b, const float* __restrict__ cw_b,
    float* __restrict__ webT, float* __restrict__ wrbT,
    float* __restrict__ Bg, float* __restrict__ obias)
{
    extern __shared__ float s[];
    const int tid = threadIdx.x;
    const int bid = blockIdx.x;

    if (bid < NBH) {
        const int bh = bid;
        const int b = bh >> 4, h = bh & 15;
        const double step = (double)(SEQ - 1) / (double)(RS - 1);

        for (int i = tid; i < RS * HD; i += 256) {
            int r = i >> 6, d = i & 63;
            int idx = (r == RS - 1) ? (SEQ - 1) : (int)((double)r * step);
            s[PR_XH + i] = x[((size_t)b * SEQ + idx) * CH + h * HD + d];
        }
        for (int i = tid; i < RS * LR; i += 256) {
            s[PR_WE + i] = we[h * RS * LR + i];
            s[PR_WR + i] = wr[h * RS * LR + i];
        }
        __syncthreads();

        for (int u = tid; u < 16 * LR; u += 256) {
            int d4 = (u & 15) * 4, e = u >> 4;
            float aE[4] = {0, 0, 0, 0}, aR[4] = {0, 0, 0, 0};
            for (int r = 0; r < RS; r++) {
                float4 xv = *(const float4*)&s[PR_XH + r * HD + d4];
                float wev = s[PR_WE + r * LR + e];
                float wrv = s[PR_WR + r * LR + e];
                aE[0] += xv.x * wev; aE[1] += xv.y * wev;
                aE[2] += xv.z * wev; aE[3] += xv.w * wev;
                aR[0] += xv.x * wrv; aR[1] += xv.y * wrv;
                aR[2] += xv.z * wrv; aR[3] += xv.w * wrv;
            }
            size_t base = (size_t)bh * LR * HD + (size_t)e * HD;
#pragma unroll
            for (int j = 0; j < 4; j++) {
                webT[base + d4 + j] = tf32r(aE[j]);
                wrbT[base + d4 + j] = tf32r(aR[j]);
            }
        }
        return;
    }
    {
        float* s_cw  = s;
        float* s_cwb = s + HD * 40;
        float* s_part = s_cwb + HD;
        for (int i = tid; i < HD * 40; i += 256) s_cw[i] = cw_w[i];
        if (tid < HD) s_cwb[tid] = cw_b[tid];
        __syncthreads();

        int idx = (bid - NBH) * 256 + tid;
        int o = idx >> 4, h = idx & 15;
        float acc[40];
#pragma unroll
        for (int j = 0; j < 40; j++) acc[j] = 0.f;
        float part = 0.f;
        const float* pr = proj_w + (size_t)o * CH + h * HD;
        for (int dp = 0; dp < HD; dp++) {
            float pv = pr[dp];
            part += pv * s_cwb[dp];
#pragma unroll
            for (int j = 0; j < 40; j++) acc[j] += pv * s_cw[dp * 40 + j];
        }
        float* dst = Bg + (size_t)o * KS2 + h * 40;
#pragma unroll
        for (int j = 0; j < 40; j++) dst[j] = tf32r(acc[j]);

        s_part[tid] = part;
        __syncthreads();
        if (h == 0) {
            float t = proj_b[o];
#pragma unroll
            for (int i = 0; i < 16; i++) t += s_part[tid + i];
            obias[o] = t;
        }
    }
}

// ---------------- gemm_qk: qk tile -> norms -> scores via tensor MMA --------
// 128 threads. smem epilogue: sv[128][132], snorm[256], Ws[40][132]
#define EP_SV   0
#define EP_NORM (128*132)
#define EP_WS   (EP_NORM + 256)
__global__ __launch_bounds__(128, 2) void gemm_qk(
    const float* __restrict__ A, const float* __restrict__ B,
    const float* __restrict__ webT, const float* __restrict__ wrbT,
    float* __restrict__ S)
{
    extern __shared__ float sm[];
    const uint32_t sbase = smem_u32(sm);
    GEMM_PROLOG();
    const int m0 = blockIdx.y * 128, n0 = blockIdx.x * 128;

    GEMM_MAINLOOP(CH, CH / BK);

    __syncthreads();

    const int b = m0 >> 11;
    const int nseq0 = m0 & 2047;
    const int c0 = blockIdx.x * 128;
    const int isK = (c0 >= 1024);
    const int h0 = isK ? ((c0 - 1024) >> 6) : (c0 >> 6);
    const int joff = isK ? LR : 0;
    const float* wsrc = isK ? wrbT : webT;

    float* sv    = sm + EP_SV;
    float* snorm = sm + EP_NORM;
    float* Ws    = sm + EP_WS;

    // (a) STS acc -> sv[n][d], tf32-rounded
#pragma unroll
    for (int mt = 0; mt < 4; mt++)
#pragma unroll
        for (int half = 0; half < 2; half++) {
            int row = wm * 64 + mt * 16 + gid + half * 8;
#pragma unroll
            for (int nt = 0; nt < 8; nt++) {
                float2 v;
                v.x = tf32r(acc[mt][nt][half * 2 + 0]);
                v.y = tf32r(acc[mt][nt][half * 2 + 1]);
                *(float2*)(sv + row * 132 + wn * 64 + nt * 8 + tig * 2) = v;
            }
        }

    // (b) stage Wpad[40][132] (zero outside head range)
    for (int i = tid; i < 40 * 132; i += 128) {
        int j40 = i / 132, c = i % 132;
        int hh = (j40 >= LR);
        int jj = j40 - hh * LR;
        float v = 0.f;
        if (c < 128 && (c >> 6) == hh)
            v = wsrc[(size_t)(b * NH + h0 + hh) * LR * HD + jj * HD + (c & 63)];
        Ws[i] = v;
    }
    __syncthreads();

    // (c) inverse norms: 256 (row, hh) units over 128 threads
    for (int u = tid; u < 256; u += 128) {
        int r = u & 127, hh = u >> 7;
        const float4* vp = (const float4*)(sv + r * 132 + hh * 64);
        float ssum = 0.f;
#pragma unroll
        for (int i = 0; i < 16; i++) {
            float4 v = vp[i];
            ssum += v.x * v.x + v.y * v.y + v.z * v.z + v.w * v.w;
        }
        snorm[r * 2 + hh] = 1.f / fmaxf(sqrtf(ssum), 1e-12f);
    }

    // (d) scores via mma: warp slab = 32 rows, R[32][40] over K=128
    float racc[2][5][4];
#pragma unroll
    for (int mtt = 0; mtt < 2; mtt++)
#pragma unroll
        for (int jt = 0; jt < 5; jt++)
#pragma unroll
            for (int r = 0; r < 4; r++) racc[mtt][jt][r] = 0.f;
    {
#pragma unroll
        for (int ks = 0; ks < 128; ks += 8) {
            float af2[2][4];
#pragma unroll
            for (int mtt = 0; mtt < 2; mtt++) {
                int r0 = (wid * 32 + mtt * 16 + gid) * 132;
                af2[mtt][0] = sv[r0 + ks + tig];
                af2[mtt][1] = sv[r0 + 8 * 132 + ks + tig];
                af2[mtt][2] = sv[r0 + ks + 4 + tig];
                af2[mtt][3] = sv[r0 + 8 * 132 + ks + 4 + tig];
            }
#pragma unroll
            for (int jt = 0; jt < 5; jt++) {
                float bf2[2];
                bf2[0] = Ws[(jt * 8 + gid) * 132 + ks + tig];
                bf2[1] = Ws[(jt * 8 + gid) * 132 + ks + 4 + tig];
#pragma unroll
                for (int mtt = 0; mtt < 2; mtt++)
                    mma8(racc[mtt][jt], af2[mtt], bf2);
            }
        }
    }
    __syncthreads();   // reads of sv done; reuse as sS[128][40]

    // (e) scale by inverse norm, stage sS
    float* sS = sm;
#pragma unroll
    for (int mtt = 0; mtt < 2; mtt++) {
        int r1 = wid * 32 + mtt * 16 + gid, r2 = r1 + 8;
#pragma unroll
        for (int jt = 0; jt < 5; jt++) {
            int j0 = jt * 8 + tig * 2;
            int hh = (j0 >= LR);
            float n1 = snorm[r1 * 2 + hh], n2 = snorm[r2 * 2 + hh];
            sS[r1 * 40 + j0]     = tf32r(racc[mtt][jt][0] * n1);
            sS[r1 * 40 + j0 + 1] = tf32r(racc[mtt][jt][1] * n1);
            sS[r2 * 40 + j0]     = tf32r(racc[mtt][jt][2] * n2);
            sS[r2 * 40 + j0 + 1] = tf32r(racc[mtt][jt][3] * n2);
        }
    }
    __syncthreads();

    // (f) coalesced store to S
    for (int it = 0; it < 32; it++) {
        int r = wid + 4 * it;
        float* dst = S + ((size_t)(b * SEQ + nseq0 + r)) * KS2 + joff;
        if (lane < LR) {
            dst[(h0)     * 40 + lane] = sS[r * 40 + lane];
            dst[(h0 + 1) * 40 + lane] = sS[r * 40 + LR + lane];
        }
    }
}

// ---------------- generic tf32 GEMM (runtime K, 128 threads) ----------------
__global__ __launch_bounds__(128, 2) void gemm_tf32(
    const float* __restrict__ A, const float* __restrict__ B,
    const float* __restrict__ bias, float* __restrict__ C,
    int Nn, int K)
{
    extern __shared__ float sm[];
    const uint32_t sbase = smem_u32(sm);
    GEMM_PROLOG();
    const int m0 = blockIdx.y * 128, n0 = blockIdx.x * 128;

    GEMM_MAINLOOP(K, K / BK);

    float bb[8][2];
#pragma unroll
    for (int nt = 0; nt < 8; nt++) {
        int col = n0 + wn * 64 + nt * 8 + tig * 2;
        bb[nt][0] = bias[col];
        bb[nt][1] = bias[col + 1];
    }
#pragma unroll
    for (int mt = 0; mt < 4; mt++)
#pragma unroll
        for (int half = 0; half < 2; half++) {
            int row = m0 + wm * 64 + mt * 16 + gid + half * 8;
            float* cp = C + (size_t)row * Nn + n0 + wn * 64 + tig * 2;
#pragma unroll
            for (int nt = 0; nt < 8; nt++) {
                float2 v;
                v.x = acc[mt][nt][half * 2 + 0] + bb[nt][0];
                v.y = acc[mt][nt][half * 2 + 1] + bb[nt][1];
                *(float2*)(cp + nt * 8) = v;
            }
        }
}

// ---------------- launch ----------------
extern "C" void kernel_launch(void* const* d_in, const int* in_sizes, int n_in,
                              void* d_out, int out_size)
{
    const float* x      = (const float*)d_in[0];
    const float* qk_w   = (const float*)d_in[1];
    const float* proj_w = (const float*)d_in[2];
    const float* proj_b = (const float*)d_in[3];
    const float* we     = (const float*)d_in[4];
    const float* wr     = (const float*)d_in[5];
    const float* cw_w   = (const float*)d_in[6];
    const float* cw_b   = (const float*)d_in[7];
    float* out = (float*)d_out;

    float *xr, *qkwr, *webT, *wrbT, *S, *Bg, *ob;
    cudaGetSymbolAddress((void**)&xr,   g_xr);
    cudaGetSymbolAddress((void**)&qkwr, g_qkwr);
    cudaGetSymbolAddress((void**)&webT, g_webT);
    cudaGetSymbolAddress((void**)&wrbT, g_wrbT);
    cudaGetSymbolAddress((void**)&S,    g_S);
    cudaGetSymbolAddress((void**)&Bg,   g_Bg);
    cudaGetSymbolAddress((void**)&ob,   g_obias);

    const int gemm_smem = 3 * STAGE_FLT * 4;                  // 98304
    cudaFuncSetAttribute(gemm_qk,
                         cudaFuncAttributeMaxDynamicSharedMemorySize, gemm_smem);
    cudaFuncSetAttribute(gemm_tf32,
                         cudaFuncAttributeMaxDynamicSharedMemorySize, gemm_smem);
    const int prep_smem = PR_TOT * 4;                         // 83200
    cudaFuncSetAttribute(prep_kernel,
                         cudaFuncAttributeMaxDynamicSharedMemorySize, prep_smem);

    // tf32 rounding of x / qk_w (also warms x in L2 for prep's gather)
    round_kernel<<<2048, 256>>>(x, qk_w, xr, qkwr);
    // gen_weights + Bg/obias
    prep_kernel<<<NBH + 64, 256, prep_smem>>>(
        x, we, wr, proj_w, cw_w, proj_b, cw_b, webT, wrbT, Bg, ob);

    // 1) qk gemm fused with normalize + tensor-core score epilogue -> S
    {
        dim3 grid(QKW / 128, MTOT / 128);
        gemm_qk<<<grid, 128, gemm_smem>>>(xr, qkwr, webT, wrbT, S);
    }
    // 2) out = S @ Bg^T + obias   (M=8192, Nn=1024, K=640)
    {
        dim3 grid(CH / 128, MTOT / 128);
        gemm_tf32<<<grid, 128, gemm_smem>>>(S, Bg, ob, out, CH, KS2);
    }
}

// round 17
// speedup vs baseline: 1.0413x; 1.0413x over previous
#include <cuda_runtime.h>
#include <cstdint>
#include <math.h>

// ---------------- problem constants ----------------
#define BCH 4
#define SEQ 2048
#define CH  1024
#define NH  16
#define HD  64
#define LR  20
#define RS  200
#define QKW (2*CH)
#define MTOT (BCH*SEQ)    // 8192
#define BK   32
#define STAGE_FLT (2*128*32)   // 32 KB per pipeline stage
#define NBH (BCH*NH)      // 64
#define KS2  640               // rank-structured K for the output gemm

// ---------------- scratch (device globals) ----------------
__device__ __align__(256) float g_xr[(size_t)MTOT * CH];
__device__ __align__(256) float g_qkwr[(size_t)QKW * CH];
__device__ __align__(256) float g_webT[(size_t)NBH * LR * HD];  // [bh][j][d]
__device__ __align__(256) float g_wrbT[(size_t)NBH * LR * HD];
__device__ __align__(256) float g_S[(size_t)MTOT * KS2];        // [b*n][h*40+j]
__device__ __align__(256) float g_Bg[(size_t)CH * KS2];         // [o][hj]
__device__ __align__(256) float g_obias[CH];

// ---------------- helpers ----------------
__device__ __forceinline__ float tf32r(float x) {
    float y;
    asm("cvt.rna.tf32.f32 %0, %1;" : "=f"(y) : "f"(x));
    return y;
}
__device__ __forceinline__ uint32_t smem_u32(const void* p) {
    uint32_t a;
    asm("{ .reg .u64 t; cvta.to.shared.u64 t, %1; cvt.u32.u64 %0, t; }"
        : "=r"(a) : "l"(p));
    return a;
}
#define CP_ASYNC16(dst, src) \
    asm volatile("cp.async.cg.shared.global [%0], [%1], 16;" :: "r"(dst), "l"(src))
#define CP_COMMIT() asm volatile("cp.async.commit_group;" ::: "memory")
#define CP_WAIT1()  asm volatile("cp.async.wait_group 1;" ::: "memory")

__device__ __forceinline__ void mma8(float* d, const float* a, const float* b) {
    asm volatile(
        "mma.sync.aligned.m16n8k8.row.col.f32.tf32.tf32.f32 "
        "{%0,%1,%2,%3}, {%4,%5,%6,%7}, {%8,%9}, {%0,%1,%2,%3};"
        : "+f"(d[0]), "+f"(d[1]), "+f"(d[2]), "+f"(d[3])
        : "r"(__float_as_uint(a[0])), "r"(__float_as_uint(a[1])),
          "r"(__float_as_uint(a[2])), "r"(__float_as_uint(a[3])),
          "r"(__float_as_uint(b[0])), "r"(__float_as_uint(b[1])));
}

// shared mainloop pieces (128 threads, 4 warps, warp tile 64x64) -------------
#define GEMM_PROLOG()                                                          \
    const int tid = threadIdx.x;                                               \
    const int wid = tid >> 5, lane = tid & 31;                                 \
    const int wm = wid >> 1;          /* 0..1 -> m offset 64*wm */             \
    const int wn = wid & 1;           /* 0..1 -> n offset 64*wn */             \
    const int gid = lane >> 2;                                                 \
    const int tig = lane & 3;                                                  \
    (void)lane;

#define COPY_STAGE(s, Kdim) do {                                               \
        const int _k0 = (s) * BK;                                              \
        const uint32_t _db = sbase + ((s) % 3) * (STAGE_FLT * 4);              \
        _Pragma("unroll")                                                      \
        for (int _i = 0; _i < 16; _i++) {                                      \
            int _id  = _i * 128 + tid;                                         \
            int _mat = _id >> 10;                                              \
            int _row = (_id >> 3) & 127;                                       \
            int _ch  = _id & 7;                                                \
            const float* _src = (_mat ? (B + (size_t)(n0 + _row) * (Kdim))     \
                                      : (A + (size_t)(m0 + _row) * (Kdim)))    \
                                + _k0 + _ch * 4;                               \
            uint32_t _dst = _db + (uint32_t)(_mat * 4096 + _row * 32 +         \
                                   ((_ch ^ (_row & 7)) << 2)) * 4u;            \
            CP_ASYNC16(_dst, _src);                                            \
        }                                                                      \
    } while (0)

#define FRAG_LOAD(ks)                                                          \
    do {                                                                       \
        const int x0 = ((((ks) >> 2)     ) ^ gid) << 2;                        \
        const int x1 = ((((ks) >> 2) + 1) ^ gid) << 2;                         \
        _Pragma("unroll")                                                      \
        for (int mt = 0; mt < 4; mt++) {                                       \
            af[mt][0] = As[mbase[mt] + x0];                                    \
            af[mt][1] = As[mbase[mt] + 256 + x0];                              \
            af[mt][2] = As[mbase[mt] + x1];                                    \
            af[mt][3] = As[mbase[mt] + 256 + x1];                              \
        }                                                                      \
        _Pragma("unroll")                                                      \
        for (int nt = 0; nt < 8; nt++) {                                       \
            bf[nt][0] = Bs[nbase[nt] + x0];                                    \
            bf[nt][1] = Bs[nbase[nt] + x1];                                    \
        }                                                                      \
    } while (0)

#define MMA_STEP()                                                             \
    _Pragma("unroll")                                                          \
    for (int mt = 0; mt < 4; mt++)                                             \
        _Pragma("unroll")                                                      \
        for (int nt = 0; nt < 8; nt++)                                         \
            mma8(acc[mt][nt], af[mt], bf[nt]);

#define GEMM_INIT()                                                            \
    float acc[4][8][4];                                                        \
    _Pragma("unroll")                                                          \
    for (int mt = 0; mt < 4; mt++)                                             \
        _Pragma("unroll")                                                      \
        for (int nt = 0; nt < 8; nt++)                                         \
            _Pragma("unroll")                                                  \
            for (int r = 0; r < 4; r++) acc[mt][nt][r] = 0.f;                  \
    int mbase[4], nbase[8];                                                    \
    _Pragma("unroll")                                                          \
    for (int mt = 0; mt < 4; mt++)                                             \
        mbase[mt] = (wm * 64 + mt * 16 + gid) * 32 + tig;                      \
    _Pragma("unroll")                                                          \
    for (int nt = 0; nt < 8; nt++)                                             \
        nbase[nt] = (wn * 64 + nt * 8 + gid) * 32 + tig;

// R15 stage order: copy issue first, then all compute (best for gemm_qk,
// which is at the 255-reg wall — holding fragments across the copy spills).
#define GEMM_MAINLOOP_A(Kdim, nst)                                             \
    COPY_STAGE(0, Kdim); CP_COMMIT();                                          \
    COPY_STAGE(1, Kdim); CP_COMMIT();                                          \
    GEMM_INIT();                                                               \
    for (int c = 0; c < (nst); c++) {                                          \
        CP_WAIT1();                                                            \
        __syncthreads();                                                       \
        if (c + 2 < (nst)) COPY_STAGE(c + 2, Kdim);                            \
        CP_COMMIT();                                                           \
        const float* As = sm + (c % 3) * STAGE_FLT;                            \
        const float* Bs = As + 4096;                                           \
        _Pragma("unroll")                                                      \
        for (int ks = 0; ks < BK; ks += 8) {                                   \
            float af[4][4], bf[8][2];                                          \
            FRAG_LOAD(ks);                                                     \
            MMA_STEP();                                                        \
        }                                                                      \
    }

// R16 stage order: first fragment load + MMA overlap the copy-issue burst
// (best for gemm_tf32, which has register slack).
#define GEMM_MAINLOOP_B(Kdim, nst)                                             \
    COPY_STAGE(0, Kdim); CP_COMMIT();                                          \
    COPY_STAGE(1, Kdim); CP_COMMIT();                                          \
    GEMM_INIT();                                                               \
    for (int c = 0; c < (nst); c++) {                                          \
        CP_WAIT1();                                                            \
        __syncthreads();                                                       \
        const float* As = sm + (c % 3) * STAGE_FLT;                            \
        const float* Bs = As + 4096;                                           \
        float af[4][4], bf[8][2];                                              \
        FRAG_LOAD(0);                                                          \
        if (c + 2 < (nst)) COPY_STAGE(c + 2, Kdim);                            \
        CP_COMMIT();                                                           \
        MMA_STEP();                                                            \
        _Pragma("unroll")                                                      \
        for (int ks = 8; ks < BK; ks += 8) {                                   \
            FRAG_LOAD(ks);                                                     \
            MMA_STEP();                                                        \
        }                                                                      \
    }

// ---------------- round pass: x and qk_w -> tf32 grid (no smem) ------------
__global__ __launch_bounds__(256) void round_kernel(
    const float* __restrict__ x, const float* __restrict__ qkw,
    float* __restrict__ xr, float* __restrict__ qkwr)
{
    const int X4 = MTOT * CH / 4;
    const int T4 = X4 + QKW * CH / 4;
    for (int i = blockIdx.x * 256 + threadIdx.x; i < T4;
         i += gridDim.x * 256) {
        if (i < X4) {
            float4 v = ((const float4*)x)[i];
            v.x = tf32r(v.x); v.y = tf32r(v.y);
            v.z = tf32r(v.z); v.w = tf32r(v.w);
            ((float4*)xr)[i] = v;
        } else {
            int j = i - X4;
            float4 v = ((const float4*)qkw)[j];
            v.x = tf32r(v.x); v.y = tf32r(v.y);
            v.z = tf32r(v.z); v.w = tf32r(v.w);
            ((float4*)qkwr)[j] = v;
        }
    }
}

// ---------------- prep: gen_weights (0..63) + gprep (64..127) ---------------
#define PR_XH 0
#define PR_WE (PR_XH + RS*HD)
#define PR_WR (PR_WE + RS*LR)
#define PR_TOT (PR_WR + RS*LR)   // 20800 floats
__global__ __launch_bounds__(256) void prep_kernel(
    const float* __restrict__ x,
    const float* __restrict__ we, const float* __restrict__ wr,
    const float* __restrict__ proj_w, const float* __restrict__ cw_w,
    const float* __restrict__ proj_b, const float* __restrict__ cw_b,
    float* __restrict__ webT, float* __restrict__ wrbT,
    float* __restrict__ Bg, float* __restrict__ obias)
{
    extern __shared__ float s[];
    const int tid = threadIdx.x;
    const int bid = blockIdx.x;

    if (bid < NBH) {
        const int bh = bid;
        const int b = bh >> 4, h = bh & 15;
        const double step = (double)(SEQ - 1) / (double)(RS - 1);

        for (int i = tid; i < RS * HD; i += 256) {
            int r = i >> 6, d = i & 63;
            int idx = (r == RS - 1) ? (SEQ - 1) : (int)((double)r * step);
            s[PR_XH + i] = x[((size_t)b * SEQ + idx) * CH + h * HD + d];
        }
        for (int i = tid; i < RS * LR; i += 256) {
            s[PR_WE + i] = we[h * RS * LR + i];
            s[PR_WR + i] = wr[h * RS * LR + i];
        }
        __syncthreads();

        for (int u = tid; u < 16 * LR; u += 256) {
            int d4 = (u & 15) * 4, e = u >> 4;
            float aE[4] = {0, 0, 0, 0}, aR[4] = {0, 0, 0, 0};
            for (int r = 0; r < RS; r++) {
                float4 xv = *(const float4*)&s[PR_XH + r * HD + d4];
                float wev = s[PR_WE + r * LR + e];
                float wrv = s[PR_WR + r * LR + e];
                aE[0] += xv.x * wev; aE[1] += xv.y * wev;
                aE[2] += xv.z * wev; aE[3] += xv.w * wev;
                aR[0] += xv.x * wrv; aR[1] += xv.y * wrv;
                aR[2] += xv.z * wrv; aR[3] += xv.w * wrv;
            }
            size_t base = (size_t)bh * LR * HD + (size_t)e * HD;
#pragma unroll
            for (int j = 0; j < 4; j++) {
                webT[base + d4 + j] = tf32r(aE[j]);
                wrbT[base + d4 + j] = tf32r(aR[j]);
            }
        }
        return;
    }
    {
        float* s_cw  = s;
        float* s_cwb = s + HD * 40;
        float* s_part = s_cwb + HD;
        for (int i = tid; i < HD * 40; i += 256) s_cw[i] = cw_w[i];
        if (tid < HD) s_cwb[tid] = cw_b[tid];
        __syncthreads();

        int idx = (bid - NBH) * 256 + tid;
        int o = idx >> 4, h = idx & 15;
        float acc[40];
#pragma unroll
        for (int j = 0; j < 40; j++) acc[j] = 0.f;
        float part = 0.f;
        const float* pr = proj_w + (size_t)o * CH + h * HD;
        for (int dp = 0; dp < HD; dp++) {
            float pv = pr[dp];
            part += pv * s_cwb[dp];
#pragma unroll
            for (int j = 0; j < 40; j++) acc[j] += pv * s_cw[dp * 40 + j];
        }
        float* dst = Bg + (size_t)o * KS2 + h * 40;
#pragma unroll
        for (int j = 0; j < 40; j++) dst[j] = tf32r(acc[j]);

        s_part[tid] = part;
        __syncthreads();
        if (h == 0) {
            float t = proj_b[o];
#pragma unroll
            for (int i = 0; i < 16; i++) t += s_part[tid + i];
            obias[o] = t;
        }
    }
}

// ---------------- gemm_qk: qk tile -> norms -> scores via tensor MMA --------
// 128 threads. smem epilogue: sv[128][132], snorm[256], Ws[40][132]
#define EP_SV   0
#define EP_NORM (128*132)
#define EP_WS   (EP_NORM + 256)
__global__ __launch_bounds__(128, 2) void gemm_qk(
    const float* __restrict__ A, const float* __restrict__ B,
    const float* __restrict__ webT, const float* __restrict__ wrbT,
    float* __restrict__ S)
{
    extern __shared__ float sm[];
    const uint32_t sbase = smem_u32(sm);
    GEMM_PROLOG();
    const int m0 = blockIdx.y * 128, n0 = blockIdx.x * 128;

    GEMM_MAINLOOP_A(CH, CH / BK);

    __syncthreads();

    const int b = m0 >> 11;
    const int nseq0 = m0 & 2047;
    const int c0 = blockIdx.x * 128;
    const int isK = (c0 >= 1024);
    const int h0 = isK ? ((c0 - 1024) >> 6) : (c0 >> 6);
    const int joff = isK ? LR : 0;
    const float* wsrc = isK ? wrbT : webT;

    float* sv    = sm + EP_SV;
    float* snorm = sm + EP_NORM;
    float* Ws    = sm + EP_WS;

    // (a) STS acc -> sv[n][d], tf32-rounded
#pragma unroll
    for (int mt = 0; mt < 4; mt++)
#pragma unroll
        for (int half = 0; half < 2; half++) {
            int row = wm * 64 + mt * 16 + gid + half * 8;
#pragma unroll
            for (int nt = 0; nt < 8; nt++) {
                float2 v;
                v.x = tf32r(acc[mt][nt][half * 2 + 0]);
                v.y = tf32r(acc[mt][nt][half * 2 + 1]);
                *(float2*)(sv + row * 132 + wn * 64 + nt * 8 + tig * 2) = v;
            }
        }

    // (b) stage Wpad[40][132] (zero outside head range)
    for (int i = tid; i < 40 * 132; i += 128) {
        int j40 = i / 132, c = i % 132;
        int hh = (j40 >= LR);
        int jj = j40 - hh * LR;
        float v = 0.f;
        if (c < 128 && (c >> 6) == hh)
            v = wsrc[(size_t)(b * NH + h0 + hh) * LR * HD + jj * HD + (c & 63)];
        Ws[i] = v;
    }
    __syncthreads();

    // (c) inverse norms: 256 (row, hh) units over 128 threads
    for (int u = tid; u < 256; u += 128) {
        int r = u & 127, hh = u >> 7;
        const float4* vp = (const float4*)(sv + r * 132 + hh * 64);
        float ssum = 0.f;
#pragma unroll
        for (int i = 0; i < 16; i++) {
            float4 v = vp[i];
            ssum += v.x * v.x + v.y * v.y + v.z * v.z + v.w * v.w;
        }
        snorm[r * 2 + hh] = 1.f / fmaxf(sqrtf(ssum), 1e-12f);
    }

    // (d) scores via mma: warp slab = 32 rows, R[32][40] over K=128
    float racc[2][5][4];
#pragma unroll
    for (int mtt = 0; mtt < 2; mtt++)
#pragma unroll
        for (int jt = 0; jt < 5; jt++)
#pragma unroll
            for (int r = 0; r < 4; r++) racc[mtt][jt][r] = 0.f;
    {
#pragma unroll
        for (int ks = 0; ks < 128; ks += 8) {
            float af2[2][4];
#pragma unroll
            for (int mtt = 0; mtt < 2; mtt++) {
                int r0 = (wid * 32 + mtt * 16 + gid) * 132;
                af2[mtt][0] = sv[r0 + ks + tig];
                af2[mtt][1] = sv[r0 + 8 * 132 + ks + tig];
                af2[mtt][2] = sv[r0 + ks + 4 + tig];
                af2[mtt][3] = sv[r0 + 8 * 132 + ks + 4 + tig];
            }
#pragma unroll
            for (int jt = 0; jt < 5; jt++) {
                float bf2[2];
                bf2[0] = Ws[(jt * 8 + gid) * 132 + ks + tig];
                bf2[1] = Ws[(jt * 8 + gid) * 132 + ks + 4 + tig];
#pragma unroll
                for (int mtt = 0; mtt < 2; mtt++)
                    mma8(racc[mtt][jt], af2[mtt], bf2);
            }
        }
    }
    __syncthreads();   // reads of sv done; reuse as sS[128][40]

    // (e) scale by inverse norm, stage sS
    float* sS = sm;
#pragma unroll
    for (int mtt = 0; mtt < 2; mtt++) {
        int r1 = wid * 32 + mtt * 16 + gid, r2 = r1 + 8;
#pragma unroll
        for (int jt = 0; jt < 5; jt++) {
            int j0 = jt * 8 + tig * 2;
            int hh = (j0 >= LR);
            float n1 = snorm[r1 * 2 + hh], n2 = snorm[r2 * 2 + hh];
            sS[r1 * 40 + j0]     = tf32r(racc[mtt][jt][0] * n1);
            sS[r1 * 40 + j0 + 1] = tf32r(racc[mtt][jt][1] * n1);
            sS[r2 * 40 + j0]     = tf32r(racc[mtt][jt][2] * n2);
            sS[r2 * 40 + j0 + 1] = tf32r(racc[mtt][jt][3] * n2);
        }
    }
    __syncthreads();

    // (f) coalesced store to S
    for (int it = 0; it < 32; it++) {
        int r = wid + 4 * it;
        float* dst = S + ((size_t)(b * SEQ + nseq0 + r)) * KS2 + joff;
        if (lane < LR) {
            dst[(h0)     * 40 + lane] = sS[r * 40 + lane];
            dst[(h0 + 1) * 40 + lane] = sS[r * 40 + LR + lane];
        }
    }
}

// ---------------- generic tf32 GEMM (runtime K, 128 threads) ----------------
__global__ __launch_bounds__(128, 2) void gemm_tf32(
    const float* __restrict__ A, const float* __restrict__ B,
    const float* __restrict__ bias, float* __restrict__ C,
    int Nn, int K)
{
    extern __shared__ float sm[];
    const uint32_t sbase = smem_u32(sm);
    GEMM_PROLOG();
    const int m0 = blockIdx.y * 128, n0 = blockIdx.x * 128;

    GEMM_MAINLOOP_B(K, K / BK);

    float bb[8][2];
#pragma unroll
    for (int nt = 0; nt < 8; nt++) {
        int col = n0 + wn * 64 + nt * 8 + tig * 2;
        bb[nt][0] = bias[col];
        bb[nt][1] = bias[col + 1];
    }
#pragma unroll
    for (int mt = 0; mt < 4; mt++)
#pragma unroll
        for (int half = 0; half < 2; half++) {
            int row = m0 + wm * 64 + mt * 16 + gid + half * 8;
            float* cp = C + (size_t)row * Nn + n0 + wn * 64 + tig * 2;
#pragma unroll
            for (int nt = 0; nt < 8; nt++) {
                float2 v;
                v.x = acc[mt][nt][half * 2 + 0] + bb[nt][0];
                v.y = acc[mt][nt][half * 2 + 1] + bb[nt][1];
                *(float2*)(cp + nt * 8) = v;
            }
        }
}

// ---------------- launch ----------------
extern "C" void kernel_launch(void* const* d_in, const int* in_sizes, int n_in,
                              void* d_out, int out_size)
{
    const float* x      = (const float*)d_in[0];
    const float* qk_w   = (const float*)d_in[1];
    const float* proj_w = (const float*)d_in[2];
    const float* proj_b = (const float*)d_in[3];
    const float* we     = (const float*)d_in[4];
    const float* wr     = (const float*)d_in[5];
    const float* cw_w   = (const float*)d_in[6];
    const float* cw_b   = (const float*)d_in[7];
    float* out = (float*)d_out;

    float *xr, *qkwr, *webT, *wrbT, *S, *Bg, *ob;
    cudaGetSymbolAddress((void**)&xr,   g_xr);
    cudaGetSymbolAddress((void**)&qkwr, g_qkwr);
    cudaGetSymbolAddress((void**)&webT, g_webT);
    cudaGetSymbolAddress((void**)&wrbT, g_wrbT);
    cudaGetSymbolAddress((void**)&S,    g_S);
    cudaGetSymbolAddress((void**)&Bg,   g_Bg);
    cudaGetSymbolAddress((void**)&ob,   g_obias);

    const int gemm_smem = 3 * STAGE_FLT * 4;                  // 98304
    cudaFuncSetAttribute(gemm_qk,
                         cudaFuncAttributeMaxDynamicSharedMemorySize, gemm_smem);
    cudaFuncSetAttribute(gemm_tf32,
                         cudaFuncAttributeMaxDynamicSharedMemorySize, gemm_smem);
    const int prep_smem = PR_TOT * 4;                         // 83200
    cudaFuncSetAttribute(prep_kernel,
                         cudaFuncAttributeMaxDynamicSharedMemorySize, prep_smem);

    // tf32 rounding of x / qk_w (also warms x in L2 for prep's gather)
    round_kernel<<<2048, 256>>>(x, qk_w, xr, qkwr);
    // gen_weights + Bg/obias
    prep_kernel<<<NBH + 64, 256, prep_smem>>>(
        x, we, wr, proj_w, cw_w, proj_b, cw_b, webT, wrbT, Bg, ob);

    // 1) qk gemm fused with normalize + tensor-core score epilogue -> S
    {
        dim3 grid(QKW / 128, MTOT / 128);
        gemm_qk<<<grid, 128, gemm_smem>>>(xr, qkwr, webT, wrbT, S);
    }
    // 2) out = S @ Bg^T + obias   (M=8192, Nn=1024, K=640)
    {
        dim3 grid(CH / 128, MTOT / 128);
        gemm_tf32<<<grid, 128, gemm_smem>>>(S, Bg, ob, out, CH, KS2);
    }
}